// round 2
// baseline (speedup 1.0000x reference)
#include <cuda_runtime.h>
#include <cuda_fp16.h>
#include <cstdint>

// Fourier-KAN: out[b,o] = bias[o] + sum_{i,k} cos(k x[b,i]) c0[i,o,k-1] + sin(k x) c1[i,o,k-1]
// B=32768, I=512, O=64, G=8  ->  GEMM M=32768, N=64, K=8192 with on-the-fly fp16 features.
// sm_103 base target: classic mma.sync (HMMA) + ldmatrix, fp32 register accumulators.

#define NB 32768
#define NI 512
#define NO 64
#define NG 8
#define KTOT 8192          // I * 2G
#define MCTA 256           // rows per CTA
#define KC 64              // K per chunk = 4 i-values * 16 features
#define NCHUNK 128         // KTOT / KC
#define NTHREADS 512

// smem: A tile 256 rows x 128B (32KB) + B tile 64 rows x 128B (8KB)
#define A_BYTES (MCTA * 128)
#define B_OFF A_BYTES
#define SMEM_BYTES (A_BYTES + 64 * 128)

// repacked coeffs: Wt[o][k], k = i*16 + f; f<8: cos freq f+1, f>=8: sin freq f-7
__device__ __half g_Wt[NO * KTOT];

// ---------------- helpers ----------------
__device__ __forceinline__ uint32_t smem_u32(const void* p) {
    uint32_t a;
    asm("{ .reg .u64 t; cvta.to.shared.u64 t, %1; cvt.u32.u64 %0, t; }" : "=r"(a) : "l"(p));
    return a;
}

#define SW128(o) ((o) ^ (((o) >> 3) & 0x70))

#define LDSM_X4(r0, r1, r2, r3, addr) \
    asm volatile("ldmatrix.sync.aligned.m8n8.x4.shared.b16 {%0,%1,%2,%3}, [%4];" \
                 : "=r"(r0), "=r"(r1), "=r"(r2), "=r"(r3) : "r"(addr))

__device__ __forceinline__ void mma16816(float* d, const uint32_t* a,
                                         uint32_t b0, uint32_t b1) {
    asm volatile(
        "mma.sync.aligned.m16n8k16.row.col.f32.f16.f16.f32 "
        "{%0,%1,%2,%3}, {%4,%5,%6,%7}, {%8,%9}, {%0,%1,%2,%3};"
        : "+f"(d[0]), "+f"(d[1]), "+f"(d[2]), "+f"(d[3])
        : "r"(a[0]), "r"(a[1]), "r"(a[2]), "r"(a[3]), "r"(b0), "r"(b1));
}

// ---------------- prep: repack coeffs (2,I,O,G) f32 -> Wt[o][k] fp16 ----------------
__global__ void fkan_prep(const float* __restrict__ cf) {
    int idx = blockIdx.x * blockDim.x + threadIdx.x;
    if (idx >= NO * KTOT) return;
    int o = idx >> 13;            // / KTOT
    int k = idx & (KTOT - 1);
    int i = k >> 4;
    int f = k & 15;
    int t = f >> 3;               // 0 = cos, 1 = sin
    int g = f & 7;                // freq-1
    float v = cf[(((t * NI) + i) * NO + o) * NG + g];
    g_Wt[o * KTOT + k] = __float2half(v);
}

// ---------------- main fused kernel ----------------
__global__ void __launch_bounds__(NTHREADS, 1)
fkan_main(const float* __restrict__ x, const float* __restrict__ bias,
          float* __restrict__ out) {
    __shared__ __align__(128) char smem[SMEM_BYTES];
    const uint32_t sbase = smem_u32(smem);

    const int tid = threadIdx.x;
    const int w = tid >> 5;
    const int lane = tid & 31;

    // ---- feature-producer assignment: row r, i-locals jb, jb+1 ----
    const int r = tid & 255;
    const int jb = (tid >> 8) << 1;          // 0 or 2
    const int brow = blockIdx.x * MCTA + r;
    const float* xrow = x + (size_t)brow * NI;
    const uint32_t a_st0 = SW128((uint32_t)(r * 128 + jb * 32));
    const uint32_t a_st1 = SW128((uint32_t)(r * 128 + jb * 32 + 16));
    const uint32_t a_st2 = SW128((uint32_t)(r * 128 + (jb + 1) * 32));
    const uint32_t a_st3 = SW128((uint32_t)(r * 128 + (jb + 1) * 32 + 16));

    // ---- B-loader assignment: 64 rows x 8 x 16B ----
    const int bn = tid >> 3;                 // 0..63
    const int bu = tid & 7;                  // 16B unit within row
    const __half* wsrc = g_Wt + bn * KTOT + bu * 8;
    const uint32_t b_sts = SW128((uint32_t)(bn * 128 + bu * 16));

    // ---- mma assignment: warp w -> rows [w*16, w*16+16) x all 64 cols ----
    const int wrow = w << 4;
    // A ldmatrix lane address pieces: row = wrow + (lane&15), half-block = (lane>>4)*16B
    const uint32_t a_row_off = (uint32_t)((wrow + (lane & 15)) * 128 + ((lane >> 4) << 4));
    // B ldmatrix lane address pieces (per 16-n group t): row = t*16 + (lane&7) + ((lane>>4)<<3)
    const uint32_t b_row_base = (uint32_t)(((lane & 7) + ((lane >> 4) << 3)) * 128 +
                                           (((lane >> 3) & 1) << 4));

    float acc[8][4];
    #pragma unroll
    for (int j = 0; j < 8; ++j)
        #pragma unroll
        for (int q = 0; q < 4; ++q) acc[j][q] = 0.0f;

    // prologue prefetch (chunk 0)
    float2 xv = *(const float2*)(xrow + jb);
    uint4 bv = *(const uint4*)(wsrc);

    #pragma unroll 1
    for (int c = 0; c < NCHUNK; ++c) {
        // prefetch next chunk (overlaps with this chunk's compute)
        float2 xn = xv;
        uint4 bvn = bv;
        if (c + 1 < NCHUNK) {
            xn = *(const float2*)(xrow + (c + 1) * 4 + jb);
            bvn = *(const uint4*)(wsrc + (c + 1) * KC);
        }

        // ---- compute 2 feature units -> A tile (smem) ----
        #pragma unroll
        for (int jj = 0; jj < 2; ++jj) {
            float xx = jj ? xv.y : xv.x;
            float s1, c1;
            __sincosf(xx, &s1, &c1);
            float t2 = c1 + c1;
            float ck[8], sk[8];
            ck[0] = c1; sk[0] = s1;
            float cm2 = 1.0f, sm2 = 0.0f;
            #pragma unroll
            for (int k = 1; k < 8; ++k) {
                float cn = fmaf(t2, ck[k - 1], -cm2);
                float sn = fmaf(t2, sk[k - 1], -sm2);
                cm2 = ck[k - 1]; sm2 = sk[k - 1];
                ck[k] = cn; sk[k] = sn;
            }
            __half2 hc0 = __floats2half2_rn(ck[0], ck[1]);
            __half2 hc1 = __floats2half2_rn(ck[2], ck[3]);
            __half2 hc2 = __floats2half2_rn(ck[4], ck[5]);
            __half2 hc3 = __floats2half2_rn(ck[6], ck[7]);
            __half2 hs0 = __floats2half2_rn(sk[0], sk[1]);
            __half2 hs1 = __floats2half2_rn(sk[2], sk[3]);
            __half2 hs2 = __floats2half2_rn(sk[4], sk[5]);
            __half2 hs3 = __floats2half2_rn(sk[6], sk[7]);
            uint4 vc, vs;
            vc.x = *(uint32_t*)&hc0; vc.y = *(uint32_t*)&hc1;
            vc.z = *(uint32_t*)&hc2; vc.w = *(uint32_t*)&hc3;
            vs.x = *(uint32_t*)&hs0; vs.y = *(uint32_t*)&hs1;
            vs.z = *(uint32_t*)&hs2; vs.w = *(uint32_t*)&hs3;
            if (jj == 0) {
                *(uint4*)(smem + a_st0) = vc;
                *(uint4*)(smem + a_st1) = vs;
            } else {
                *(uint4*)(smem + a_st2) = vc;
                *(uint4*)(smem + a_st3) = vs;
            }
        }

        // ---- B chunk -> smem ----
        *(uint4*)(smem + B_OFF + b_sts) = bv;

        __syncthreads();

        // ---- ldmatrix + mma over 4 K16-steps ----
        #pragma unroll
        for (int ks = 0; ks < 4; ++ks) {
            uint32_t a[4];
            LDSM_X4(a[0], a[1], a[2], a[3],
                    sbase + SW128(a_row_off + ks * 32));
            uint32_t b[16];
            #pragma unroll
            for (int t = 0; t < 4; ++t) {
                LDSM_X4(b[4 * t + 0], b[4 * t + 1], b[4 * t + 2], b[4 * t + 3],
                        sbase + B_OFF +
                        SW128(b_row_base + (uint32_t)(t * 16 * 128) + ks * 32));
            }
            #pragma unroll
            for (int j = 0; j < 8; ++j) {
                int t = j >> 1;
                int hi = (j & 1) << 1;
                mma16816(acc[j], a, b[4 * t + hi], b[4 * t + hi + 1]);
            }
        }

        __syncthreads();
        xv = xn; bv = bvn;
    }

    // ---- epilogue: acc (+bias) -> out ----
    const int gr = lane >> 2;
    const int gc = (lane & 3) << 1;
    const int row0 = blockIdx.x * MCTA + wrow + gr;
    #pragma unroll
    for (int j = 0; j < 8; ++j) {
        int col = j * 8 + gc;
        float2 bb = *(const float2*)(bias + col);
        float2 v0, v1;
        v0.x = acc[j][0] + bb.x; v0.y = acc[j][1] + bb.y;
        v1.x = acc[j][2] + bb.x; v1.y = acc[j][3] + bb.y;
        *(float2*)(out + (size_t)row0 * NO + col) = v0;
        *(float2*)(out + (size_t)(row0 + 8) * NO + col) = v1;
    }
}

// ---------------- launch ----------------
extern "C" void kernel_launch(void* const* d_in, const int* in_sizes, int n_in,
                              void* d_out, int out_size) {
    const float* x    = (const float*)d_in[0];
    const float* cf   = (const float*)d_in[1];
    const float* bias = (const float*)d_in[2];
    float* out        = (float*)d_out;

    fkan_prep<<<(NO * KTOT + 255) / 256, 256>>>(cf);
    fkan_main<<<NB / MCTA, NTHREADS>>>(x, bias, out);
}

// round 3
// speedup vs baseline: 1.0871x; 1.0871x over previous
#include <cuda_runtime.h>
#include <cuda_fp16.h>
#include <cstdint>

// Fourier-KAN: out[b,o] = bias[o] + sum_{i,k} cos(k x[b,i]) c0[i,o,k-1] + sin(k x) c1[i,o,k-1]
// B=32768, I=512, O=64, G=8  ->  GEMM M=32768, N=64, K=8192, fp16 features on the fly.
// sm_103 base: mma.sync m16n8k16 + ldmatrix. Warp tile 32x32 (8x2 grid), double-buffered
// smem, one __syncthreads per K-chunk with producer/consumer overlap.

#define NB 32768
#define NI 512
#define NO 64
#define NG 8
#define KTOT 8192
#define MCTA 256
#define KC 64              // K per chunk = 4 i-values * 16 features
#define NCHUNK 128
#define NTHREADS 512

#define ABYTES (MCTA * 128)        // 32 KB
#define BBYTES (64 * 128)          // 8 KB
#define BUFSZ  (ABYTES + BBYTES)   // 40 KB (1024-aligned)
#define SMEM_TOTAL (2 * BUFSZ)     // 80 KB

// repacked coeffs: Wt[o][k], k = i*16 + f; f<8: cos freq f+1, f>=8: sin freq f-7
__device__ __half g_Wt[NO * KTOT];

// ---------------- helpers ----------------
__device__ __forceinline__ uint32_t smem_u32(const void* p) {
    uint32_t a;
    asm("{ .reg .u64 t; cvta.to.shared.u64 t, %1; cvt.u32.u64 %0, t; }" : "=r"(a) : "l"(p));
    return a;
}

#define SW128(o) ((o) ^ (((o) >> 3) & 0x70))

#define LDSM_X4(r0, r1, r2, r3, addr) \
    asm volatile("ldmatrix.sync.aligned.m8n8.x4.shared.b16 {%0,%1,%2,%3}, [%4];" \
                 : "=r"(r0), "=r"(r1), "=r"(r2), "=r"(r3) : "r"(addr))

__device__ __forceinline__ void mma16816(float* d, const uint32_t* a,
                                         uint32_t b0, uint32_t b1) {
    asm volatile(
        "mma.sync.aligned.m16n8k16.row.col.f32.f16.f16.f32 "
        "{%0,%1,%2,%3}, {%4,%5,%6,%7}, {%8,%9}, {%0,%1,%2,%3};"
        : "+f"(d[0]), "+f"(d[1]), "+f"(d[2]), "+f"(d[3])
        : "r"(a[0]), "r"(a[1]), "r"(a[2]), "r"(a[3]), "r"(b0), "r"(b1));
}

// ---------------- prep: repack coeffs (2,I,O,G) f32 -> Wt[o][k] fp16 ----------------
__global__ void fkan_prep(const float* __restrict__ cf) {
    int idx = blockIdx.x * blockDim.x + threadIdx.x;
    if (idx >= NO * KTOT) return;
    int o = idx >> 13;
    int k = idx & (KTOT - 1);
    int i = k >> 4;
    int f = k & 15;
    int t = f >> 3;               // 0 = cos, 1 = sin
    int g = f & 7;                // freq-1
    float v = cf[(((t * NI) + i) * NO + o) * NG + g];
    g_Wt[o * KTOT + k] = __float2half(v);
}

// ---------------- main fused kernel ----------------
__global__ void __launch_bounds__(NTHREADS, 1)
fkan_main(const float* __restrict__ x, const float* __restrict__ bias,
          float* __restrict__ out) {
    extern __shared__ __align__(1024) char smem[];
    const uint32_t sbase = smem_u32(smem);

    const int tid = threadIdx.x;
    const int w = tid >> 5;
    const int lane = tid & 31;
    const int wr = w & 7;               // warp row (8): rows wr*32..+31
    const int wc = w >> 3;              // warp col (2): cols wc*32..+31

    // ---- feature-producer assignment: row r, i-locals jb, jb+1 ----
    const int r = tid & 255;
    const int jb = (tid >> 8) << 1;
    const int brow = blockIdx.x * MCTA + r;
    const float* xrow = x + (size_t)brow * NI;
    const uint32_t fst0 = SW128((uint32_t)(r * 128 + jb * 32));
    const uint32_t fst1 = SW128((uint32_t)(r * 128 + jb * 32 + 16));
    const uint32_t fst2 = SW128((uint32_t)(r * 128 + (jb + 1) * 32));
    const uint32_t fst3 = SW128((uint32_t)(r * 128 + (jb + 1) * 32 + 16));

    // ---- B-loader assignment: 64 rows x 8 x 16B ----
    const int bn = tid >> 3;
    const int bu = tid & 7;
    const __half* wsrc = g_Wt + bn * KTOT + bu * 8;
    const uint32_t b_sts = SW128((uint32_t)(bn * 128 + bu * 16));

    // ---- ldmatrix lane addresses (swizzled base; XOR ks*32 inside loop) ----
    const uint32_t a_ls0 = SW128((uint32_t)((wr * 32 + (lane & 15)) * 128 +
                                            ((lane >> 4) << 4)));
    const uint32_t a_ls1 = SW128((uint32_t)((wr * 32 + 16 + (lane & 15)) * 128 +
                                            ((lane >> 4) << 4)));
    const uint32_t bl = (uint32_t)((lane & 7) + ((lane >> 4) << 3));
    const uint32_t bb = (uint32_t)(((lane >> 3) & 1) << 4);
    const uint32_t b_ls0 = SW128((uint32_t)((wc * 32 + bl) * 128) + bb);
    const uint32_t b_ls1 = SW128((uint32_t)((wc * 32 + 16 + bl) * 128) + bb);

    float acc[2][4][4];
    #pragma unroll
    for (int t = 0; t < 2; ++t)
        #pragma unroll
        for (int j = 0; j < 4; ++j)
            #pragma unroll
            for (int q = 0; q < 4; ++q) acc[t][j][q] = 0.0f;

    // ---- feature compute + STS (chunk data in xv) ----
    auto produce = [&](float2 xv, uint4 bv, uint32_t bufo) {
        #pragma unroll
        for (int jj = 0; jj < 2; ++jj) {
            float xx = jj ? xv.y : xv.x;
            float s1, c1;
            __sincosf(xx, &s1, &c1);
            float t2 = c1 + c1;
            float ck[8], sk[8];
            ck[0] = c1; sk[0] = s1;
            float cm2 = 1.0f, sm2 = 0.0f;
            #pragma unroll
            for (int k = 1; k < 8; ++k) {
                float cn = fmaf(t2, ck[k - 1], -cm2);
                float sn = fmaf(t2, sk[k - 1], -sm2);
                cm2 = ck[k - 1]; sm2 = sk[k - 1];
                ck[k] = cn; sk[k] = sn;
            }
            __half2 h[8];
            h[0] = __floats2half2_rn(ck[0], ck[1]);
            h[1] = __floats2half2_rn(ck[2], ck[3]);
            h[2] = __floats2half2_rn(ck[4], ck[5]);
            h[3] = __floats2half2_rn(ck[6], ck[7]);
            h[4] = __floats2half2_rn(sk[0], sk[1]);
            h[5] = __floats2half2_rn(sk[2], sk[3]);
            h[6] = __floats2half2_rn(sk[4], sk[5]);
            h[7] = __floats2half2_rn(sk[6], sk[7]);
            uint4 vc, vs;
            vc.x = *(uint32_t*)&h[0]; vc.y = *(uint32_t*)&h[1];
            vc.z = *(uint32_t*)&h[2]; vc.w = *(uint32_t*)&h[3];
            vs.x = *(uint32_t*)&h[4]; vs.y = *(uint32_t*)&h[5];
            vs.z = *(uint32_t*)&h[6]; vs.w = *(uint32_t*)&h[7];
            if (jj == 0) {
                *(uint4*)(smem + bufo + fst0) = vc;
                *(uint4*)(smem + bufo + fst1) = vs;
            } else {
                *(uint4*)(smem + bufo + fst2) = vc;
                *(uint4*)(smem + bufo + fst3) = vs;
            }
        }
        *(uint4*)(smem + bufo + ABYTES + b_sts) = bv;
    };

    // ---- prologue: chunk 0 into buf 0 ----
    float2 xv = *(const float2*)(xrow + jb);
    uint4 bv = *(const uint4*)(wsrc);
    produce(xv, bv, 0);
    // prefetch chunk 1
    xv = *(const float2*)(xrow + 4 + jb);
    bv = *(const uint4*)(wsrc + KC);
    __syncthreads();

    #pragma unroll 1
    for (int c = 0; c < NCHUNK; ++c) {
        const uint32_t cur = (uint32_t)(c & 1) * BUFSZ;
        const uint32_t nxt = cur ^ BUFSZ;
        const uint32_t aB = sbase + cur;
        const uint32_t bB = sbase + cur + ABYTES;

        // prefetch chunk c+2 (clamped)
        const int cp = (c + 2 < NCHUNK) ? c + 2 : NCHUNK - 1;
        float2 xn = *(const float2*)(xrow + cp * 4 + jb);
        uint4 bvn = *(const uint4*)(wsrc + cp * KC);

        // ---- MMA for chunk c from buffer cur ----
        #pragma unroll
        for (int ks = 0; ks < 4; ++ks) {
            const uint32_t kx = (uint32_t)(ks * 32);
            uint32_t a0[4], a1[4], b0[4], b1[4];
            LDSM_X4(a0[0], a0[1], a0[2], a0[3], aB + (a_ls0 ^ kx));
            LDSM_X4(a1[0], a1[1], a1[2], a1[3], aB + (a_ls1 ^ kx));
            LDSM_X4(b0[0], b0[1], b0[2], b0[3], bB + (b_ls0 ^ kx));
            LDSM_X4(b1[0], b1[1], b1[2], b1[3], bB + (b_ls1 ^ kx));
            #pragma unroll
            for (int j = 0; j < 4; ++j) {
                uint32_t* bp = (j < 2) ? b0 : b1;
                const int hi = (j & 1) << 1;
                mma16816(acc[0][j], a0, bp[hi], bp[hi + 1]);
                mma16816(acc[1][j], a1, bp[hi], bp[hi + 1]);
            }
        }

        // ---- produce chunk c+1 into buffer nxt (overlaps MMA across warps) ----
        if (c + 1 < NCHUNK) produce(xv, bv, nxt);

        xv = xn; bv = bvn;
        __syncthreads();
    }

    // ---- epilogue: acc (+bias) -> out ----
    const int gr = lane >> 2;
    const int gc = (lane & 3) << 1;
    #pragma unroll
    for (int t = 0; t < 2; ++t) {
        const int row0 = blockIdx.x * MCTA + wr * 32 + t * 16 + gr;
        #pragma unroll
        for (int j = 0; j < 4; ++j) {
            const int col = wc * 32 + j * 8 + gc;
            float2 bb2 = *(const float2*)(bias + col);
            float2 v0, v1;
            v0.x = acc[t][j][0] + bb2.x; v0.y = acc[t][j][1] + bb2.y;
            v1.x = acc[t][j][2] + bb2.x; v1.y = acc[t][j][3] + bb2.y;
            *(float2*)(out + (size_t)row0 * NO + col) = v0;
            *(float2*)(out + (size_t)(row0 + 8) * NO + col) = v1;
        }
    }
}

// ---------------- launch ----------------
extern "C" void kernel_launch(void* const* d_in, const int* in_sizes, int n_in,
                              void* d_out, int out_size) {
    const float* x    = (const float*)d_in[0];
    const float* cf   = (const float*)d_in[1];
    const float* bias = (const float*)d_in[2];
    float* out        = (float*)d_out;

    static bool attr_set = false;
    if (!attr_set) {
        cudaFuncSetAttribute(fkan_main, cudaFuncAttributeMaxDynamicSharedMemorySize,
                             SMEM_TOTAL);
        attr_set = true;
    }

    fkan_prep<<<(NO * KTOT + 255) / 256, 256>>>(cf);
    fkan_main<<<NB / MCTA, NTHREADS, SMEM_TOTAL>>>(x, bias, out);
}

// round 4
// speedup vs baseline: 1.2464x; 1.1466x over previous
#include <cuda_runtime.h>
#include <cuda_fp16.h>
#include <cstdint>

// Fourier-KAN: out[b,o] = bias[o] + sum_{i,k} cos(k x[b,i]) c0[i,o,k-1] + sin(k x) c1[i,o,k-1]
// B=32768, I=512, O=64, G=8  ->  GEMM M=32768, N=64, K=8192, fp16 features on the fly.
// sm_103 base: mma.sync m16n8k16 + ldmatrix. Warp grid (m=8, n=1, k=2): each warp does
// 32 rows x 64 cols x half the K-chunk. Cuts LDSM smem traffic 128->96 KB per chunk.
// Cross-warp K-reduction once in the epilogue. Double-buffered smem, one sync per chunk.

#define NB 32768
#define NI 512
#define NO 64
#define NG 8
#define KTOT 8192
#define MCTA 256
#define KC 64              // K per chunk = 4 i-values * 16 features
#define NCHUNK 128
#define NTHREADS 512

#define ABYTES (MCTA * 128)        // 32 KB
#define BBYTES (64 * 128)          // 8 KB
#define BUFSZ  (ABYTES + BBYTES)   // 40 KB
#define SMEM_TOTAL (2 * BUFSZ)     // 80 KB (epilogue reduction reuses 64 KB of this)

// repacked coeffs: Wt[o][k], k = i*16 + f; f<8: cos freq f+1, f>=8: sin freq f-7
__device__ __half g_Wt[NO * KTOT];

// ---------------- helpers ----------------
__device__ __forceinline__ uint32_t smem_u32(const void* p) {
    uint32_t a;
    asm("{ .reg .u64 t; cvta.to.shared.u64 t, %1; cvt.u32.u64 %0, t; }" : "=r"(a) : "l"(p));
    return a;
}

#define SW128(o) ((o) ^ (((o) >> 3) & 0x70))

#define LDSM_X4(r0, r1, r2, r3, addr) \
    asm volatile("ldmatrix.sync.aligned.m8n8.x4.shared.b16 {%0,%1,%2,%3}, [%4];" \
                 : "=r"(r0), "=r"(r1), "=r"(r2), "=r"(r3) : "r"(addr))

__device__ __forceinline__ void mma16816(float* d, const uint32_t* a,
                                         uint32_t b0, uint32_t b1) {
    asm volatile(
        "mma.sync.aligned.m16n8k16.row.col.f32.f16.f16.f32 "
        "{%0,%1,%2,%3}, {%4,%5,%6,%7}, {%8,%9}, {%0,%1,%2,%3};"
        : "+f"(d[0]), "+f"(d[1]), "+f"(d[2]), "+f"(d[3])
        : "r"(a[0]), "r"(a[1]), "r"(a[2]), "r"(a[3]), "r"(b0), "r"(b1));
}

// ---------------- prep: repack coeffs (2,I,O,G) f32 -> Wt[o][k] fp16 ----------------
__global__ void fkan_prep(const float* __restrict__ cf) {
    int idx = blockIdx.x * blockDim.x + threadIdx.x;
    if (idx >= NO * KTOT) return;
    int o = idx >> 13;
    int k = idx & (KTOT - 1);
    int i = k >> 4;
    int f = k & 15;
    int t = f >> 3;               // 0 = cos, 1 = sin
    int g = f & 7;                // freq-1
    float v = cf[(((t * NI) + i) * NO + o) * NG + g];
    g_Wt[o * KTOT + k] = __float2half(v);
}

// ---------------- main fused kernel ----------------
__global__ void __launch_bounds__(NTHREADS, 1)
fkan_main(const float* __restrict__ x, const float* __restrict__ bias,
          float* __restrict__ out) {
    extern __shared__ __align__(1024) char smem[];
    const uint32_t sbase = smem_u32(smem);

    const int tid = threadIdx.x;
    const int w = tid >> 5;
    const int lane = tid & 31;
    const int mw = w & 7;               // m-warp: rows mw*32..+31
    const int kh = w >> 3;              // k-half: 0 -> K[0,32), 1 -> K[32,64)
    const uint32_t khx = (uint32_t)(kh << 6);   // 64-byte XOR offset

    // ---- feature-producer assignment: row r, i-locals jb, jb+1 ----
    const int r = tid & 255;
    const int jb = (tid >> 8) << 1;
    const int brow = blockIdx.x * MCTA + r;
    const float* xrow = x + (size_t)brow * NI;
    const uint32_t fst0 = SW128((uint32_t)(r * 128 + jb * 32));
    const uint32_t fst1 = SW128((uint32_t)(r * 128 + jb * 32 + 16));
    const uint32_t fst2 = SW128((uint32_t)(r * 128 + (jb + 1) * 32));
    const uint32_t fst3 = SW128((uint32_t)(r * 128 + (jb + 1) * 32 + 16));

    // ---- B-loader assignment: 64 rows x 8 x 16B ----
    const int bn = tid >> 3;
    const int bu = tid & 7;
    const __half* wsrc = g_Wt + bn * KTOT + bu * 8;
    const uint32_t b_sts = SW128((uint32_t)(bn * 128 + bu * 16));

    // ---- ldmatrix lane bases (kx applied by XOR: bits 5/6 only, carry-free) ----
    const uint32_t a_ls0 = SW128((uint32_t)((mw * 32 + (lane & 15)) * 128 +
                                            ((lane >> 4) << 4)));
    const uint32_t a_ls1 = SW128((uint32_t)((mw * 32 + 16 + (lane & 15)) * 128 +
                                            ((lane >> 4) << 4)));
    const uint32_t bl = (uint32_t)((lane & 7) + ((lane >> 4) << 3));
    const uint32_t bbo = (uint32_t)(((lane >> 3) & 1) << 4);
    uint32_t b_ls[4];
    #pragma unroll
    for (int t = 0; t < 4; ++t)
        b_ls[t] = SW128((uint32_t)((t * 16 + bl) * 128 + bbo));

    float acc[2][8][4];
    #pragma unroll
    for (int mi = 0; mi < 2; ++mi)
        #pragma unroll
        for (int j = 0; j < 8; ++j)
            #pragma unroll
            for (int q = 0; q < 4; ++q) acc[mi][j][q] = 0.0f;

    // ---- feature compute + STS ----
    auto produce = [&](float2 xv, uint4 bv, uint32_t bufo) {
        #pragma unroll
        for (int jj = 0; jj < 2; ++jj) {
            float xx = jj ? xv.y : xv.x;
            float s1, c1;
            __sincosf(xx, &s1, &c1);
            float t2 = c1 + c1;
            float ck[8], sk[8];
            ck[0] = c1; sk[0] = s1;
            float cm2 = 1.0f, sm2 = 0.0f;
            #pragma unroll
            for (int k = 1; k < 8; ++k) {
                float cn = fmaf(t2, ck[k - 1], -cm2);
                float sn = fmaf(t2, sk[k - 1], -sm2);
                cm2 = ck[k - 1]; sm2 = sk[k - 1];
                ck[k] = cn; sk[k] = sn;
            }
            __half2 h[8];
            h[0] = __floats2half2_rn(ck[0], ck[1]);
            h[1] = __floats2half2_rn(ck[2], ck[3]);
            h[2] = __floats2half2_rn(ck[4], ck[5]);
            h[3] = __floats2half2_rn(ck[6], ck[7]);
            h[4] = __floats2half2_rn(sk[0], sk[1]);
            h[5] = __floats2half2_rn(sk[2], sk[3]);
            h[6] = __floats2half2_rn(sk[4], sk[5]);
            h[7] = __floats2half2_rn(sk[6], sk[7]);
            uint4 vc, vs;
            vc.x = *(uint32_t*)&h[0]; vc.y = *(uint32_t*)&h[1];
            vc.z = *(uint32_t*)&h[2]; vc.w = *(uint32_t*)&h[3];
            vs.x = *(uint32_t*)&h[4]; vs.y = *(uint32_t*)&h[5];
            vs.z = *(uint32_t*)&h[6]; vs.w = *(uint32_t*)&h[7];
            if (jj == 0) {
                *(uint4*)(smem + bufo + fst0) = vc;
                *(uint4*)(smem + bufo + fst1) = vs;
            } else {
                *(uint4*)(smem + bufo + fst2) = vc;
                *(uint4*)(smem + bufo + fst3) = vs;
            }
        }
        *(uint4*)(smem + bufo + ABYTES + b_sts) = bv;
    };

    // ---- prologue: chunk 0 into buf 0 ----
    float2 xv = *(const float2*)(xrow + jb);
    uint4 bv = *(const uint4*)(wsrc);
    produce(xv, bv, 0);
    xv = *(const float2*)(xrow + 4 + jb);
    bv = *(const uint4*)(wsrc + KC);
    __syncthreads();

    #pragma unroll 1
    for (int c = 0; c < NCHUNK; ++c) {
        const uint32_t cur = (uint32_t)(c & 1) * BUFSZ;
        const uint32_t nxt = cur ^ BUFSZ;
        const uint32_t aB = sbase + cur;
        const uint32_t bB = sbase + cur + ABYTES;

        // prefetch chunk c+2 (clamped)
        const int cp = (c + 2 < NCHUNK) ? c + 2 : NCHUNK - 1;
        float2 xn = *(const float2*)(xrow + cp * 4 + jb);
        uint4 bvn = *(const uint4*)(wsrc + cp * KC);

        // ---- MMA: this warp's K-half (2 x k16 steps), rows mw*32..+31, all 64 cols ----
        #pragma unroll
        for (int ks = 0; ks < 2; ++ks) {
            const uint32_t kx = khx ^ (uint32_t)(ks << 5);
            uint32_t a0[4], a1[4], b[16];
            LDSM_X4(a0[0], a0[1], a0[2], a0[3], aB + (a_ls0 ^ kx));
            LDSM_X4(a1[0], a1[1], a1[2], a1[3], aB + (a_ls1 ^ kx));
            #pragma unroll
            for (int t = 0; t < 4; ++t)
                LDSM_X4(b[4 * t], b[4 * t + 1], b[4 * t + 2], b[4 * t + 3],
                        bB + (b_ls[t] ^ kx));
            #pragma unroll
            for (int j = 0; j < 8; ++j) {
                const int t = j >> 1;
                const int hi = (j & 1) << 1;
                mma16816(acc[0][j], a0, b[4 * t + hi], b[4 * t + hi + 1]);
                mma16816(acc[1][j], a1, b[4 * t + hi], b[4 * t + hi + 1]);
            }
        }

        // ---- produce chunk c+1 into the other buffer ----
        if (c + 1 < NCHUNK) produce(xv, bv, nxt);

        xv = xn; bv = bvn;
        __syncthreads();
    }

    // ---- K-reduction: warps 8-15 (kh=1) park partials in smem; warps 0-7 add ----
    // per m-warp region: 32 rows x 64 cols fp32 = 8 KB at mw*8192
    {
        if (kh == 1) {
            #pragma unroll
            for (int mi = 0; mi < 2; ++mi)
                #pragma unroll
                for (int j = 0; j < 8; ++j) {
                    const uint32_t off = (uint32_t)(mw * 8192 +
                                         ((mi * 8 + j) * 32 + lane) * 16);
                    *(float4*)(smem + off) = *(float4*)acc[mi][j];
                }
        }
        __syncthreads();
        if (kh == 0) {
            #pragma unroll
            for (int mi = 0; mi < 2; ++mi)
                #pragma unroll
                for (int j = 0; j < 8; ++j) {
                    const uint32_t off = (uint32_t)(mw * 8192 +
                                         ((mi * 8 + j) * 32 + lane) * 16);
                    float4 p = *(const float4*)(smem + off);
                    acc[mi][j][0] += p.x; acc[mi][j][1] += p.y;
                    acc[mi][j][2] += p.z; acc[mi][j][3] += p.w;
                }
        }
    }

    // ---- epilogue: acc (+bias) -> out (warps 0-7 only) ----
    if (kh == 0) {
        const int gr = lane >> 2;
        const int gc = (lane & 3) << 1;
        #pragma unroll
        for (int mi = 0; mi < 2; ++mi) {
            const int row0 = blockIdx.x * MCTA + mw * 32 + mi * 16 + gr;
            #pragma unroll
            for (int j = 0; j < 8; ++j) {
                const int col = j * 8 + gc;
                float2 bb2 = *(const float2*)(bias + col);
                float2 v0, v1;
                v0.x = acc[mi][j][0] + bb2.x; v0.y = acc[mi][j][1] + bb2.y;
                v1.x = acc[mi][j][2] + bb2.x; v1.y = acc[mi][j][3] + bb2.y;
                *(float2*)(out + (size_t)row0 * NO + col) = v0;
                *(float2*)(out + (size_t)(row0 + 8) * NO + col) = v1;
            }
        }
    }
}

// ---------------- launch ----------------
extern "C" void kernel_launch(void* const* d_in, const int* in_sizes, int n_in,
                              void* d_out, int out_size) {
    const float* x    = (const float*)d_in[0];
    const float* cf   = (const float*)d_in[1];
    const float* bias = (const float*)d_in[2];
    float* out        = (float*)d_out;

    static bool attr_set = false;
    if (!attr_set) {
        cudaFuncSetAttribute(fkan_main, cudaFuncAttributeMaxDynamicSharedMemorySize,
                             SMEM_TOTAL);
        attr_set = true;
    }

    fkan_prep<<<(NO * KTOT + 255) / 256, 256>>>(cf);
    fkan_main<<<NB / MCTA, NTHREADS, SMEM_TOTAL>>>(x, bias, out);
}